// round 14
// baseline (speedup 1.0000x reference)
#include <cuda_runtime.h>
#include <cuda_fp16.h>
#include <mma.h>
#include <cstdint>

using namespace nvcuda;

#define N_NODES 50000
#define E_EDGES 800000
#define IN_C 128
#define HID 64
#define HEADS 4
#define C1 (HEADS * HID)   // 256
#define OUT_C 64
#define NEG_SLOPE 0.2f
#define NBLK 49            // ceil(50000/1024)

// ---------------- scratch (static device globals; zero-initialized) ------------
__device__ __half g_h1h[(size_t)N_NODES * C1];
__device__ float g_h1post[(size_t)N_NODES * C1];
__device__ __half g_h2h[(size_t)N_NODES * OUT_C];
__device__ float g_asrc1[N_NODES * HEADS];
__device__ float g_adst1[N_NODES * HEADS];
__device__ float g_asrc2[N_NODES];
__device__ float g_adst2[N_NODES];
__device__ int g_deg[N_NODES];      // zeroed by agg1 each call (zero at load)
__device__ int g_cursor[N_NODES];   // zeroed by agg1 each call (zero at load)
__device__ int g_rowstart[N_NODES + 1];
__device__ int g_bsum[NBLK];
__device__ int g_csr[E_EDGES];
__device__ int g_is64;

// ---------------- helpers ----------------
__device__ __forceinline__ float lrelu(float x) { return x > 0.f ? x : NEG_SLOPE * x; }
__device__ __forceinline__ float elu(float x)   { return x > 0.f ? x : __expf(x) - 1.f; }

__device__ __forceinline__ int load_idx(const void* ei, long long pos) {
    if (g_is64) return (int)((const long long*)ei)[pos];
    return ((const int*)ei)[pos];
}

// Detect int64 vs int32 edge_index (odd int32 words all zero => int64).
__global__ void detect_kernel(const int* ei) {
    __shared__ int nz;
    if (threadIdx.x == 0) nz = 0;
    __syncthreads();
    for (int i = threadIdx.x; i < 1024; i += blockDim.x)
        if (ei[2 * i + 1] != 0) atomicOr(&nz, 1);
    __syncthreads();
    if (threadIdx.x == 0) g_is64 = (nz == 0) ? 1 : 0;
}

__global__ void deg_kernel(const void* ei, int E) {
    int i = blockIdx.x * blockDim.x + threadIdx.x;
    if (i >= E) return;
    int dst = load_idx(ei, (long long)E + i);
    atomicAdd(&g_deg[dst], 1);
}

// ---------------- 2-kernel scan of g_deg -> g_rowstart -------------------------
__global__ void scan1_kernel() {  // per-block sums (1024 items/block)
    __shared__ int red[256];
    int b = blockIdx.x, t = threadIdx.x;
    int base = b * 1024 + t * 4;
    int s = 0;
    if (base + 3 < N_NODES) {
        int4 v = *(const int4*)&g_deg[base];
        s = v.x + v.y + v.z + v.w;
    } else {
#pragma unroll
        for (int k = 0; k < 4; ++k)
            if (base + k < N_NODES) s += g_deg[base + k];
    }
    red[t] = s;
    __syncthreads();
#pragma unroll
    for (int off = 128; off; off >>= 1) {
        if (t < off) red[t] += red[t + off];
        __syncthreads();
    }
    if (t == 0) g_bsum[b] = red[0];
}

// local exclusive scan + per-block offset (each block reduces bsum[0..b-1] itself)
__global__ void scanB_kernel() {
    __shared__ int pre[64];
    __shared__ int red[256];
    int b = blockIdx.x, t = threadIdx.x;
    if (t < 64) pre[t] = (t < b && t < NBLK) ? g_bsum[t] : 0;
    __syncthreads();
    if (t < 32) { pre[t] += pre[t + 32]; }
    __syncthreads();
    if (t < 16) { pre[t] += pre[t + 16]; }
    __syncthreads();
    if (t < 8) { pre[t] += pre[t + 8]; }
    __syncthreads();
    if (t < 4) { pre[t] += pre[t + 4]; }
    __syncthreads();
    if (t < 2) { pre[t] += pre[t + 2]; }
    __syncthreads();
    if (t == 0) { pre[0] += pre[1]; }
    __syncthreads();
    int boff = pre[0];

    int base = b * 1024 + t * 4;
    int v[4] = {0, 0, 0, 0};
    if (base + 3 < N_NODES) {
        int4 q = *(const int4*)&g_deg[base];
        v[0] = q.x; v[1] = q.y; v[2] = q.z; v[3] = q.w;
    } else {
#pragma unroll
        for (int k = 0; k < 4; ++k)
            if (base + k < N_NODES) v[k] = g_deg[base + k];
    }
    red[t] = v[0] + v[1] + v[2] + v[3];
    __syncthreads();
    for (int off = 1; off < 256; off <<= 1) {
        int u = (t >= off) ? red[t - off] : 0;
        __syncthreads();
        red[t] += u;
        __syncthreads();
    }
    int run = boff + (t ? red[t - 1] : 0);
#pragma unroll
    for (int k = 0; k < 4; ++k) {
        if (base + k < N_NODES) {
            g_rowstart[base + k] = run;
            run += v[k];
            if (base + k == N_NODES - 1) g_rowstart[N_NODES] = run;
        }
    }
}

__global__ void scatter_kernel(const void* ei, int E) {
    int i = blockIdx.x * blockDim.x + threadIdx.x;
    if (i >= E) return;
    int src = load_idx(ei, i);
    int dst = load_idx(ei, (long long)E + i);
    int pos = g_rowstart[dst] + atomicAdd(&g_cursor[dst], 1);
    g_csr[pos] = src;
}

// ---------------- WMMA GEMM (fp16 in, fp32 accum) + fused dot epilogue ---------
#define WBM 128
#define WBN 64
#define WBK 32
#define WLDA (WBK + 8)    // 40 halves = 80 B
#define WLDB (WBN + 8)    // 72 halves = 144 B
#define WLDC (WBN + 4)    // 68 floats = 272 B (16B-multiple)
#define AS_BYTES (WBM * WLDA * 2)
#define AB_BYTES (AS_BYTES + WBK * WLDB * 2)
#define CS_BYTES (WBM * WLDC * 4)
#define SM_BYTES (CS_BYTES > AB_BYTES ? CS_BYTES : AB_BYTES)

__global__ void __launch_bounds__(256)
gemm_wmma_fused(const float* __restrict__ A, const float* __restrict__ B,
                __half* __restrict__ Oh,
                float* __restrict__ aSrc, float* __restrict__ aDst,
                const float* __restrict__ attS, const float* __restrict__ attD,
                int aStride, int M, int N, int K) {
    __shared__ __align__(32) char smbuf[SM_BYTES];
    __half* As = (__half*)smbuf;
    __half* Bs = (__half*)(smbuf + AS_BYTES);
    float* Cs = (float*)smbuf;

    const int tid = threadIdx.x;
    const int wid = tid >> 5;
    const int wm = wid >> 1;
    const int wn = wid & 1;
    const int bm0 = blockIdx.y * WBM;
    const int bn0 = blockIdx.x * WBN;

    wmma::fragment<wmma::accumulator, 16, 16, 16, float> acc[2][2];
#pragma unroll
    for (int i = 0; i < 2; ++i)
#pragma unroll
        for (int j = 0; j < 2; ++j) wmma::fill_fragment(acc[i][j], 0.f);

    for (int k0 = 0; k0 < K; k0 += WBK) {
#pragma unroll
        for (int it = 0; it < (WBM * WBK) / (4 * 256); ++it) {
            int f = tid + it * 256;
            int r = f >> 3;
            int c4 = f & 7;
            int row = bm0 + r;
            float4 v = make_float4(0.f, 0.f, 0.f, 0.f);
            if (row < M) v = *(const float4*)(A + (size_t)row * K + k0 + c4 * 4);
            __half2* d = (__half2*)&As[r * WLDA + c4 * 4];
            d[0] = __floats2half2_rn(v.x, v.y);
            d[1] = __floats2half2_rn(v.z, v.w);
        }
#pragma unroll
        for (int it = 0; it < (WBK * WBN) / (4 * 256); ++it) {
            int f = tid + it * 256;
            int r = f >> 4;
            int c4 = f & 15;
            float4 v = *(const float4*)(B + (size_t)(k0 + r) * N + bn0 + c4 * 4);
            __half2* d = (__half2*)&Bs[r * WLDB + c4 * 4];
            d[0] = __floats2half2_rn(v.x, v.y);
            d[1] = __floats2half2_rn(v.z, v.w);
        }
        __syncthreads();
#pragma unroll
        for (int kk = 0; kk < WBK; kk += 16) {
            wmma::fragment<wmma::matrix_a, 16, 16, 16, __half, wmma::row_major> af[2];
            wmma::fragment<wmma::matrix_b, 16, 16, 16, __half, wmma::row_major> bf[2];
#pragma unroll
            for (int i = 0; i < 2; ++i)
                wmma::load_matrix_sync(af[i], &As[(wm * 32 + i * 16) * WLDA + kk], WLDA);
#pragma unroll
            for (int j = 0; j < 2; ++j)
                wmma::load_matrix_sync(bf[j], &Bs[kk * WLDB + wn * 32 + j * 16], WLDB);
#pragma unroll
            for (int i = 0; i < 2; ++i)
#pragma unroll
                for (int j = 0; j < 2; ++j)
                    wmma::mma_sync(acc[i][j], af[i], bf[j], acc[i][j]);
        }
        __syncthreads();
    }

#pragma unroll
    for (int i = 0; i < 2; ++i)
#pragma unroll
        for (int j = 0; j < 2; ++j)
            wmma::store_matrix_sync(&Cs[(wm * 32 + i * 16) * WLDC + wn * 32 + j * 16],
                                    acc[i][j], WLDC, wmma::mem_row_major);
    __syncthreads();

    const int r = tid >> 1;
    const int hf = tid & 1;
    const int cb = hf * 32;
    const int row = bm0 + r;
    float ps = 0.f, pd = 0.f;
    float4 v4[8];
#pragma unroll
    for (int q = 0; q < 8; ++q) {
        v4[q] = *(const float4*)&Cs[r * WLDC + cb + q * 4];
        const float* vv = (const float*)&v4[q];
#pragma unroll
        for (int u = 0; u < 4; ++u) {
            ps = fmaf(vv[u], attS[bn0 + cb + q * 4 + u], ps);
            pd = fmaf(vv[u], attD[bn0 + cb + q * 4 + u], pd);
        }
    }
    ps += __shfl_xor_sync(0xffffffffu, ps, 1);
    pd += __shfl_xor_sync(0xffffffffu, pd, 1);
    if (row < M) {
        __half2 h2[16];
        const float* vals = (const float*)v4;
#pragma unroll
        for (int j = 0; j < 16; ++j)
            h2[j] = __floats2half2_rn(vals[2 * j], vals[2 * j + 1]);
        uint4* op = (uint4*)(Oh + (size_t)row * N + bn0 + cb);
        const uint4* hp = (const uint4*)h2;
        op[0] = hp[0]; op[1] = hp[1]; op[2] = hp[2]; op[3] = hp[3];
        if (hf == 0) {
            int aIdx = bn0 >> 6;
            aSrc[(size_t)row * aStride + aIdx] = ps;
            aDst[(size_t)row * aStride + aIdx] = pd;
        }
    }
}

// ---------------- fused segment-softmax + aggregation, layer 1 ----------------
// 2 warps per node; each warp owns 128 channels (2 heads); lane owns 4 channels.
// No max-pass (bounded exponents).
__global__ void agg1_kernel(const float* __restrict__ b1) {
    int gw = (blockIdx.x * blockDim.x + threadIdx.x) >> 5;
    if (gw >= 2 * N_NODES) return;
    int lane = threadIdx.x & 31;
    int n = gw >> 1;
    int half = gw & 1;
    int cb = half * 128 + lane * 4;      // 4 channels per lane
    int head = cb >> 6;                  // half*2 + (lane>>4)

    float4 ad = *(const float4*)(g_adst1 + n * 4);
    float4 an = *(const float4*)(g_asrc1 + n * 4);
    float adsel = head == 0 ? ad.x : head == 1 ? ad.y : head == 2 ? ad.z : ad.w;
    float ansel = head == 0 ? an.x : head == 1 ? an.y : head == 2 ? an.z : an.w;
    float wself = __expf(lrelu(ansel + adsel));
    bool dlead = (lane & 15) == 0;
    float denomAcc = dlead ? wself : 0.f;
    int beg = g_rowstart[n], end = g_rowstart[n + 1];

    uint2 qs = *(const uint2*)(g_h1h + (size_t)n * C1 + cb);
    const __half2* hp = (const __half2*)&qs;
    float2 f0 = __half22float2(hp[0]), f1 = __half22float2(hp[1]);
    float a0 = wself * f0.x, a1 = wself * f0.y, a2 = wself * f1.x, a3 = wself * f1.y;

    // zero deg/cursor for next invocation
    if (lane == 0 && half == 0) { g_deg[n] = 0; g_cursor[n] = 0; }

    int j = beg;
    for (; j + 1 < end; j += 2) {
        int s0 = g_csr[j];
        int s1 = g_csr[j + 1];
        float4 as0 = *(const float4*)(g_asrc1 + (size_t)s0 * 4);
        float4 as1 = *(const float4*)(g_asrc1 + (size_t)s1 * 4);
        uint2 q0 = *(const uint2*)(g_h1h + (size_t)s0 * C1 + cb);
        uint2 q1 = *(const uint2*)(g_h1h + (size_t)s1 * C1 + cb);
        {
            float asel = head == 0 ? as0.x : head == 1 ? as0.y : head == 2 ? as0.z : as0.w;
            float wv = __expf(lrelu(asel + adsel));
            if (dlead) denomAcc += wv;
            const __half2* qp = (const __half2*)&q0;
            float2 g0 = __half22float2(qp[0]), g1 = __half22float2(qp[1]);
            a0 = fmaf(wv, g0.x, a0); a1 = fmaf(wv, g0.y, a1);
            a2 = fmaf(wv, g1.x, a2); a3 = fmaf(wv, g1.y, a3);
        }
        {
            float asel = head == 0 ? as1.x : head == 1 ? as1.y : head == 2 ? as1.z : as1.w;
            float wv = __expf(lrelu(asel + adsel));
            if (dlead) denomAcc += wv;
            const __half2* qp = (const __half2*)&q1;
            float2 g0 = __half22float2(qp[0]), g1 = __half22float2(qp[1]);
            a0 = fmaf(wv, g0.x, a0); a1 = fmaf(wv, g0.y, a1);
            a2 = fmaf(wv, g1.x, a2); a3 = fmaf(wv, g1.y, a3);
        }
    }
    if (j < end) {
        int s = g_csr[j];
        float4 as = *(const float4*)(g_asrc1 + (size_t)s * 4);
        float asel = head == 0 ? as.x : head == 1 ? as.y : head == 2 ? as.z : as.w;
        float wv = __expf(lrelu(asel + adsel));
        if (dlead) denomAcc += wv;
        uint2 q = *(const uint2*)(g_h1h + (size_t)s * C1 + cb);
        const __half2* qp = (const __half2*)&q;
        float2 g0 = __half22float2(qp[0]), g1 = __half22float2(qp[1]);
        a0 = fmaf(wv, g0.x, a0); a1 = fmaf(wv, g0.y, a1);
        a2 = fmaf(wv, g1.x, a2); a3 = fmaf(wv, g1.y, a3);
    }
    // broadcast denom from the leader of this lane's 16-lane head group
    float denom = __shfl_sync(0xffffffffu, denomAcc, lane & 16);
    float inv = 1.f / (denom + 1e-16f);
    float4 o;
    o.x = elu(a0 * inv + b1[cb + 0]);
    o.y = elu(a1 * inv + b1[cb + 1]);
    o.z = elu(a2 * inv + b1[cb + 2]);
    o.w = elu(a3 * inv + b1[cb + 3]);
    *(float4*)(g_h1post + (size_t)n * C1 + cb) = o;
}

// ---------------- fused segment-softmax + aggregation, layer 2 ----------------
__global__ void agg2_kernel(const float* __restrict__ b2, float* __restrict__ out) {
    int gw = (blockIdx.x * blockDim.x + threadIdx.x) >> 5;
    if (gw >= N_NODES) return;
    int lane = threadIdx.x & 31;
    int n = gw;
    float ad = g_adst2[n];
    float wself = __expf(lrelu(g_asrc2[n] + ad));
    float denomAcc = (lane == 0) ? wself : 0.f;
    int beg = g_rowstart[n], end = g_rowstart[n + 1];
    float2 hn = __half22float2(*(const __half2*)(g_h2h + (size_t)n * OUT_C + lane * 2));
    float a0 = wself * hn.x, a1 = wself * hn.y;
    int j = beg;
    for (; j + 1 < end; j += 2) {
        int s0 = g_csr[j], s1 = g_csr[j + 1];
        float e0 = g_asrc2[s0], e1 = g_asrc2[s1];
        float2 q0 = __half22float2(*(const __half2*)(g_h2h + (size_t)s0 * OUT_C + lane * 2));
        float2 q1 = __half22float2(*(const __half2*)(g_h2h + (size_t)s1 * OUT_C + lane * 2));
        float w0 = __expf(lrelu(e0 + ad));
        float w1 = __expf(lrelu(e1 + ad));
        if (lane == 0) denomAcc += w0 + w1;
        a0 = fmaf(w0, q0.x, a0);
        a1 = fmaf(w0, q0.y, a1);
        a0 = fmaf(w1, q1.x, a0);
        a1 = fmaf(w1, q1.y, a1);
    }
    if (j < end) {
        int s = g_csr[j];
        float w = __expf(lrelu(g_asrc2[s] + ad));
        if (lane == 0) denomAcc += w;
        float2 q = __half22float2(*(const __half2*)(g_h2h + (size_t)s * OUT_C + lane * 2));
        a0 = fmaf(w, q.x, a0);
        a1 = fmaf(w, q.y, a1);
    }
    float denom = __shfl_sync(0xffffffffu, denomAcc, 0);
    float inv = 1.f / (denom + 1e-16f);
    float2 o;
    o.x = elu(a0 * inv + b2[lane * 2 + 0]);
    o.y = elu(a1 * inv + b2[lane * 2 + 1]);
    *(float2*)(out + (size_t)n * OUT_C + lane * 2) = o;
}

// ---------------- launch ----------------
extern "C" void kernel_launch(void* const* d_in, const int* in_sizes, int n_in,
                              void* d_out, int out_size) {
    const float* x     = (const float*)d_in[0];
    const void*  ei    = d_in[1];
    const float* W1    = (const float*)d_in[3];
    const float* attS1 = (const float*)d_in[4];
    const float* attD1 = (const float*)d_in[5];
    const float* b1    = (const float*)d_in[6];
    const float* W2    = (const float*)d_in[7];
    const float* attS2 = (const float*)d_in[8];
    const float* attD2 = (const float*)d_in[9];
    const float* b2    = (const float*)d_in[10];
    float* out = (float*)d_out;
    int E = in_sizes[1] / 2;

    void *p_h1h = nullptr, *p_h1post = nullptr, *p_h2h = nullptr;
    void *p_as1 = nullptr, *p_ad1 = nullptr, *p_as2 = nullptr, *p_ad2 = nullptr;
    cudaGetSymbolAddress(&p_h1h, g_h1h);
    cudaGetSymbolAddress(&p_h1post, g_h1post);
    cudaGetSymbolAddress(&p_h2h, g_h2h);
    cudaGetSymbolAddress(&p_as1, g_asrc1);
    cudaGetSymbolAddress(&p_ad1, g_adst1);
    cudaGetSymbolAddress(&p_as2, g_asrc2);
    cudaGetSymbolAddress(&p_ad2, g_adst2);

    cudaStreamCaptureStatus cst = cudaStreamCaptureStatusNone;
    cudaStreamIsCapturing(0, &cst);
    bool capturing = (cst != cudaStreamCaptureStatusNone);

    cudaStream_t s1;
    cudaStreamCreateWithFlags(&s1, cudaStreamNonBlocking);
    cudaEvent_t ev0, ev1;
    cudaEventCreateWithFlags(&ev0, cudaEventDisableTiming);
    cudaEventCreateWithFlags(&ev1, cudaEventDisableTiming);

    // fork: CSR build on s1, GEMM1 on origin stream
    cudaEventRecord(ev0, 0);
    cudaStreamWaitEvent(s1, ev0, 0);

    detect_kernel<<<1, 256, 0, s1>>>((const int*)ei);
    deg_kernel<<<(E + 255) / 256, 256, 0, s1>>>(ei, E);
    scan1_kernel<<<NBLK, 256, 0, s1>>>();
    scanB_kernel<<<NBLK, 256, 0, s1>>>();
    scatter_kernel<<<(E + 255) / 256, 256, 0, s1>>>(ei, E);
    cudaEventRecord(ev1, s1);

    dim3 g1(C1 / WBN, (N_NODES + WBM - 1) / WBM);   // (4, 391)
    gemm_wmma_fused<<<g1, 256>>>(
        x, W1, (__half*)p_h1h, (float*)p_as1, (float*)p_ad1,
        attS1, attD1, HEADS, N_NODES, C1, IN_C);

    cudaStreamWaitEvent(0, ev1, 0);
    agg1_kernel<<<(2 * N_NODES + 7) / 8, 256>>>(b1);

    dim3 g2(OUT_C / WBN, (N_NODES + WBM - 1) / WBM);  // (1, 391)
    gemm_wmma_fused<<<g2, 256>>>(
        (const float*)p_h1post, W2, (__half*)p_h2h, (float*)p_as2, (float*)p_ad2,
        attS2, attD2, 1, N_NODES, OUT_C, C1);

    agg2_kernel<<<(N_NODES + 7) / 8, 256>>>(b2, out);

    if (!capturing) {
        cudaEventDestroy(ev0);
        cudaEventDestroy(ev1);
        cudaStreamDestroy(s1);
    }
}